// round 12
// baseline (speedup 1.0000x reference)
#include <cuda_runtime.h>
#include <math.h>

#define Bb 4
#define Ss 2048
#define Dd 256
#define Rr (Bb*Ss)

// ------------------- scratch (device globals; no allocation) ---------------
__device__ __align__(16) float g_M[Dd*Dd];   // M = Wq^T Wk
__device__ __align__(16) float g_c1[Dd], g_c2[Dd];
__device__ float g_c0;
__device__ float g_mean[Rr], g_inv[Rr];      // LN stats
// per-d-half partial reductions (half 0: cols 0..127, half 1: cols 128..255)
__device__ float g_pd[2*Rr], g_pm[2*Rr], g_pa1[2*Rr], g_pa2[2*Rr];
__device__ float g_diag[Rr];
__device__ double g_l[Rr], g_P[Rr];
__device__ int g_lo[Rr], g_hi[Rr];

// ------------------- K1: prologue = LN stats (1024) + M (256) + bias (1) ---
__global__ void prologue_kernel(const float* __restrict__ ctx,
                                const float* __restrict__ Wq,
                                const float* __restrict__ Wk,
                                const float* __restrict__ bq,
                                const float* __restrict__ bk) {
    int bid = blockIdx.x;
    int t = threadIdx.x;
    if (bid < 1024) {
        int w = t >> 5, lane = t & 31;
        int r = bid * 8 + w;
        const float* src = ctx + (size_t)r * Dd;
        float4 v0 = *(const float4*)&src[lane*4];
        float4 v1 = *(const float4*)&src[128 + lane*4];
        float s = v0.x+v0.y+v0.z+v0.w + v1.x+v1.y+v1.z+v1.w;
        #pragma unroll
        for (int o = 16; o; o >>= 1) s += __shfl_xor_sync(0xffffffffu, s, o);
        float mean = s * (1.0f/Dd);
        float d0x=v0.x-mean, d0y=v0.y-mean, d0z=v0.z-mean, d0w=v0.w-mean;
        float d1x=v1.x-mean, d1y=v1.y-mean, d1z=v1.z-mean, d1w=v1.w-mean;
        float sq = d0x*d0x+d0y*d0y+d0z*d0z+d0w*d0w + d1x*d1x+d1y*d1y+d1z*d1z+d1w*d1w;
        #pragma unroll
        for (int o = 16; o; o >>= 1) sq += __shfl_xor_sync(0xffffffffu, sq, o);
        if (lane == 0) {
            g_mean[r] = mean;
            g_inv[r] = 1.0f / (sqrtf(sq * (1.0f/(Dd-1))) + 1e-6f);
        }
    } else if (bid < 1280) {
        __shared__ float sq[16][17], sk[16][17];
        int mb = bid - 1024;
        int bx = mb & 15, by = mb >> 4;
        int tx = t & 15, ty = t >> 4;
        float acc = 0.f;
        for (int f0 = 0; f0 < Dd; f0 += 16) {
            sq[ty][tx] = Wq[(f0+ty)*Dd + by*16 + tx];
            sk[ty][tx] = Wk[(f0+ty)*Dd + bx*16 + tx];
            __syncthreads();
            #pragma unroll
            for (int f = 0; f < 16; ++f) acc += sq[f][ty] * sk[f][tx];
            __syncthreads();
        }
        g_M[(by*16+ty)*Dd + bx*16 + tx] = acc;
    } else {
        __shared__ float red[256];
        float a1 = 0.f, a2 = 0.f;
        for (int f = 0; f < Dd; ++f) {
            a1 += Wq[f*Dd + t] * bk[f];
            a2 += Wk[f*Dd + t] * bq[f];
        }
        g_c1[t] = a1; g_c2[t] = a2;
        red[t] = bq[t] * bk[t];
        __syncthreads();
        for (int s = 128; s; s >>= 1) { if (t < s) red[t] += red[t+s]; __syncthreads(); }
        if (t == 0) g_c0 = red[0];
    }
}

// ------------------- helpers -----------------------------------------------
__device__ __forceinline__ float4 ln4(float4 v, float4 l4, float4 b4, float mn, float iv) {
    return make_float4(l4.x*iv*(v.x-mn)+b4.x, l4.y*iv*(v.y-mn)+b4.y,
                       l4.z*iv*(v.z-mn)+b4.z, l4.w*iv*(v.w-mn)+b4.w);
}
__device__ __forceinline__ float dot4(float4 a, float4 b) {
    return a.x*b.x + a.y*b.y + a.z*b.z + a.w*b.w;
}

// ------------------- K2: GEMM + fused dot-reductions -----------------------
// U[r] = M x_r in registers. Epilogue: u_row.x_{row+1} = dotm[row+1],
// u_row.x_{row-1} = dotp[row-1]  (dotp[r] := x_r^T M x_{r+1} = q_r.k_{r+1}).
__global__ void __launch_bounds__(256) gemm_kernel(const float* __restrict__ ctx,
                                                   const float* __restrict__ la,
                                                   const float* __restrict__ lb) {
    __shared__ __align__(16) float As[16][132];
    __shared__ __align__(16) float Bs[16][132];
    int tid = threadIdx.x;
    int tx = tid & 15;
    int ty = tid >> 4;
    int d0 = blockIdx.x * 128;
    int r0 = blockIdx.y * 128;

    int rowL[2], segL[2];
    float mnL[2], ivL[2];
    #pragma unroll
    for (int s = 0; s < 2; ++s) {
        int idx = tid + s*256;
        rowL[s] = idx >> 2; segL[s] = (idx & 3) * 4;
        mnL[s] = g_mean[r0 + rowL[s]];
        ivL[s] = g_inv[r0 + rowL[s]];
    }

    float acc[8][8] = {};
    float4 pa[2], pb[2];

    #pragma unroll
    for (int s = 0; s < 2; ++s) {
        float4 v  = *(const float4*)&ctx[(size_t)(r0+rowL[s])*Dd + segL[s]];
        float4 l4 = *(const float4*)&la[segL[s]];
        float4 b4 = *(const float4*)&lb[segL[s]];
        pa[s] = ln4(v, l4, b4, mnL[s], ivL[s]);
        pb[s] = *(const float4*)&g_M[(size_t)(d0+rowL[s])*Dd + segL[s]];
    }

    for (int e0 = 0; e0 < Dd; e0 += 16) {
        #pragma unroll
        for (int s = 0; s < 2; ++s) {
            int row = rowL[s], seg = segL[s];
            As[seg+0][row] = pa[s].x; As[seg+1][row] = pa[s].y;
            As[seg+2][row] = pa[s].z; As[seg+3][row] = pa[s].w;
            Bs[seg+0][row] = pb[s].x; Bs[seg+1][row] = pb[s].y;
            Bs[seg+2][row] = pb[s].z; Bs[seg+3][row] = pb[s].w;
        }
        __syncthreads();
        if (e0 + 16 < Dd) {
            #pragma unroll
            for (int s = 0; s < 2; ++s) {
                int e = e0 + 16 + segL[s];
                float4 v  = *(const float4*)&ctx[(size_t)(r0+rowL[s])*Dd + e];
                float4 l4 = *(const float4*)&la[e];
                float4 b4 = *(const float4*)&lb[e];
                pa[s] = ln4(v, l4, b4, mnL[s], ivL[s]);
                pb[s] = *(const float4*)&g_M[(size_t)(d0+rowL[s])*Dd + e];
            }
        }
        #pragma unroll
        for (int k = 0; k < 16; ++k) {
            float4 a0 = *(const float4*)&As[k][ty*4];
            float4 a1 = *(const float4*)&As[k][ty*4 + 64];
            float4 b0 = *(const float4*)&Bs[k][tx*4];
            float4 b1 = *(const float4*)&Bs[k][tx*4 + 64];
            float av[8] = {a0.x,a0.y,a0.z,a0.w, a1.x,a1.y,a1.z,a1.w};
            float bv[8] = {b0.x,b0.y,b0.z,b0.w, b1.x,b1.y,b1.z,b1.w};
            #pragma unroll
            for (int i2 = 0; i2 < 8; ++i2)
                #pragma unroll
                for (int j2 = 0; j2 < 8; ++j2) acc[i2][j2] += av[i2]*bv[j2];
        }
        __syncthreads();
    }

    // ---- epilogue: fused per-row reductions over this block's 128 cols ----
    int cA = d0 + tx*4, cB = d0 + 64 + tx*4;
    float4 laA = *(const float4*)&la[cA];
    float4 laB = *(const float4*)&la[cB];
    float4 lbA = *(const float4*)&lb[cA];
    float4 lbB = *(const float4*)&lb[cB];
    float4 c1A = *(const float4*)&g_c1[cA];
    float4 c1B = *(const float4*)&g_c1[cB];
    float4 c2A = *(const float4*)&g_c2[cA];
    float4 c2B = *(const float4*)&g_c2[cB];
    size_t pbase = (size_t)blockIdx.x * Rr;

    #pragma unroll
    for (int ri = 0; ri < 2; ++ri) {
        #pragma unroll
        for (int i2 = 0; i2 < 4; ++i2) {
            int row = r0 + ri*64 + ty*4 + i2;
            const float* u = acc[ri*4 + i2];

            float mn = g_mean[row], iv = g_inv[row];
            float4 xA = ln4(*(const float4*)&ctx[(size_t)row*Dd + cA], laA, lbA, mn, iv);
            float4 xB = ln4(*(const float4*)&ctx[(size_t)row*Dd + cB], laB, lbB, mn, iv);
            float pa1 = dot4(xA, c1A) + dot4(xB, c1B);
            float pa2 = dot4(xA, c2A) + dot4(xB, c2B);

            int rp = (row + 1 < Rr) ? row + 1 : Rr - 1;   // clamped load; store guarded
            float mnp = g_mean[rp], ivp = g_inv[rp];
            float4 ppA = ln4(*(const float4*)&ctx[(size_t)rp*Dd + cA], laA, lbA, mnp, ivp);
            float4 ppB = ln4(*(const float4*)&ctx[(size_t)rp*Dd + cB], laB, lbB, mnp, ivp);
            float dmv = u[0]*ppA.x + u[1]*ppA.y + u[2]*ppA.z + u[3]*ppA.w
                      + u[4]*ppB.x + u[5]*ppB.y + u[6]*ppB.z + u[7]*ppB.w;  // = dotm[row+1]

            int rm = (row - 1 >= 0) ? row - 1 : 0;        // clamped load; store guarded
            float mnm = g_mean[rm], ivm = g_inv[rm];
            float4 pmA = ln4(*(const float4*)&ctx[(size_t)rm*Dd + cA], laA, lbA, mnm, ivm);
            float4 pmB = ln4(*(const float4*)&ctx[(size_t)rm*Dd + cB], laB, lbB, mnm, ivm);
            float dpv = u[0]*pmA.x + u[1]*pmA.y + u[2]*pmA.z + u[3]*pmA.w
                      + u[4]*pmB.x + u[5]*pmB.y + u[6]*pmB.z + u[7]*pmB.w;  // = dotp[row-1]

            #pragma unroll
            for (int o = 1; o < 16; o <<= 1) {
                dmv += __shfl_xor_sync(0xffffffffu, dmv, o);
                dpv += __shfl_xor_sync(0xffffffffu, dpv, o);
                pa1 += __shfl_xor_sync(0xffffffffu, pa1, o);
                pa2 += __shfl_xor_sync(0xffffffffu, pa2, o);
            }
            if (tx == 0) {
                g_pa1[pbase + row] = pa1;
                g_pa2[pbase + row] = pa2;
                if (row + 1 < Rr) g_pm[pbase + row + 1] = dmv;  // dotm[row+1]
                if (row - 1 >= 0) g_pd[pbase + row - 1] = dpv;  // dotp[row-1]
            }
        }
    }
}

// ------------------- probs helper (sums the two d-half partials) -----------
__device__ __forceinline__ void probs(const int* __restrict__ ebase, int i, int r,
                                      float& pp, float& pm, float& ps) {
    bool ap = (i < Ss-1) && (ebase[(size_t)i*Ss + i + 1] != 0);
    bool am = (i > 0)    && (ebase[(size_t)i*Ss + i - 1] != 0);
    if (!ap && !am) { pp = pm = ps = 1.0f/(float)Ss; return; }
    ps = 0.f;
    if (ap && am) {
        float c0 = g_c0;
        float dotp = g_pd[r] + g_pd[Rr + r];
        float dotm = g_pm[r] + g_pm[Rr + r];
        float a1   = g_pa1[r] + g_pa1[Rr + r];
        float a2p  = g_pa2[r+1] + g_pa2[Rr + r+1];
        float a2m  = g_pa2[r-1] + g_pa2[Rr + r-1];
        float sp = (dotp + a1 + a2p + c0) * (1.0f/256.0f);
        float sm = (dotm + a1 + a2m + c0) * (1.0f/256.0f);
        float m = fmaxf(sp, sm);
        float ep = expf(sp - m), em = expf(sm - m);
        float inv = 1.0f/(ep + em);
        pp = ep*inv; pm = em*inv;
    } else if (ap) { pp = 1.f; pm = 0.f; }
    else           { pp = 0.f; pm = 1.f; }
}

// ------------------- K3: wide probs + log + diag ---------------------------
__global__ void lprob_kernel(const int* __restrict__ eos,
                             const float* __restrict__ prior) {
    int r = blockIdx.x*64 + threadIdx.x;
    if (r >= Rr) return;
    int b = r >> 11, i = r & (Ss-1);
    const int* ebase = eos + (size_t)b*Ss*Ss;
    const float* pbase = prior + (size_t)b*Ss*Ss;

    float pp, pm, ps;
    probs(ebase, i, r, pp, pm, ps);

    if (i < Ss-1) {
        float pp2, pm2, ps2;
        probs(ebase, i+1, r+1, pp2, pm2, ps2);
        float n1 = sqrtf(pp*pm2 + 1e-9f);
        float pr = pbase[(size_t)i*Ss + i + 1];
        float nb = pr + (1.0f - pr)*n1;
        g_l[r] = log((double)nb + 1e-9);
    } else {
        g_l[r] = 0.0;
    }
    float nd = sqrtf(ps*ps + 1e-9f);
    float pr = pbase[(size_t)i*Ss + i];
    g_diag[r] = pr + (1.0f - pr)*nd;
}

// ------------------- K4: fused scan + band (4 blocks, P stays in smem) -----
__global__ void scanband_kernel() {
    __shared__ double wsum[32];
    __shared__ double Ps[Ss];
    int b = blockIdx.x, t = threadIdx.x;
    int lane = t & 31, w = t >> 5;
    int base = b*Ss;
    double l0 = g_l[base + 2*t];
    double l1 = g_l[base + 2*t + 1];
    double s = l0 + l1;
    double v = s;
    #pragma unroll
    for (int o = 1; o < 32; o <<= 1) {
        double n = __shfl_up_sync(0xffffffffu, v, o);
        if (lane >= o) v += n;
    }
    if (lane == 31) wsum[w] = v;
    __syncthreads();
    if (w == 0) {
        double x = wsum[lane];
        #pragma unroll
        for (int o = 1; o < 32; o <<= 1) {
            double n = __shfl_up_sync(0xffffffffu, x, o);
            if (lane >= o) x += n;
        }
        wsum[lane] = x;
    }
    __syncthreads();
    double off = (w > 0) ? wsum[w-1] : 0.0;
    double excl = off + v - s;
    Ps[2*t]   = excl;
    Ps[2*t+1] = excl + l0;
    g_P[base + 2*t]     = excl;
    g_P[base + 2*t + 1] = excl + l0;
    __syncthreads();

    const double T = 46.0;   // exp(-46) ~ 1e-20 << 1e-9 floor
    #pragma unroll
    for (int q = 0; q < 2; ++q) {
        int i = 2*t + q;
        double Pi = Ps[i];
        int lo2 = i, hi2 = Ss-1;
        while (lo2 < hi2) {
            int mid = (lo2 + hi2 + 1) >> 1;
            if (Pi - Ps[mid] <= T) lo2 = mid; else hi2 = mid - 1;
        }
        int a = 0, b2 = i;
        while (a < b2) {
            int mid = (a + b2) >> 1;
            if (Ps[mid] - Pi <= T) b2 = mid; else a = mid + 1;
        }
        g_lo[base+i] = a; g_hi[base+i] = lo2;
    }
}

// ------------------- K5: banded output, 4 rows/block, float4 ---------------
__global__ void out_kernel(float* __restrict__ out) {
    int r0 = blockIdx.x * 4;
    #pragma unroll
    for (int rr = 0; rr < 4; ++rr) {
        int r = r0 + rr;
        int b = r >> 11, i = r & (Ss-1);
        const double* P = g_P + b*Ss;
        double Pi = P[i];
        int lo = g_lo[r], hi = g_hi[r];
        float dg = g_diag[r];
        float* orow = out + (size_t)r*Ss;
        #pragma unroll
        for (int s = 0; s < 2; ++s) {
            int t = threadIdx.x + s*256;
            int j0 = t*4;
            float4 o;
            if (j0 + 3 < lo || j0 > hi) {
                o = make_float4(1e-9f, 1e-9f, 1e-9f, 1e-9f);
            } else {
                float v[4];
                #pragma unroll
                for (int q = 0; q < 4; ++q) {
                    int j = j0 + q;
                    float x;
                    if (j < lo || j > hi) x = 1e-9f;
                    else if (j == i)      x = dg;
                    else {
                        double e = (j > i) ? (P[j] - Pi) : (Pi - P[j]);
                        x = expf((float)e) + 1e-9f;
                    }
                    v[q] = x;
                }
                o = make_float4(v[0], v[1], v[2], v[3]);
            }
            *(float4*)&orow[j0] = o;
        }
    }
}

// ------------------- launch -------------------------------------------------
extern "C" void kernel_launch(void* const* d_in, const int* in_sizes, int n_in,
                              void* d_out, int out_size) {
    const float* ctx   = (const float*)d_in[0];
    const float* prior = (const float*)d_in[1];
    const float* Wq    = (const float*)d_in[2];
    const float* bq    = (const float*)d_in[3];
    const float* Wk    = (const float*)d_in[4];
    const float* bk    = (const float*)d_in[5];
    const float* la    = (const float*)d_in[6];
    const float* lb    = (const float*)d_in[7];
    const int*   eos   = (const int*)d_in[8];
    float* out = (float*)d_out;

    prologue_kernel<<<1281, 256>>>(ctx, Wq, Wk, bq, bk);
    gemm_kernel<<<dim3(2, Rr/128), 256>>>(ctx, la, lb);
    lprob_kernel<<<Rr/64, 64>>>(eos, prior);
    scanband_kernel<<<Bb, 1024>>>();
    out_kernel<<<Rr/4, 256>>>(out);
}

// round 13
// speedup vs baseline: 1.2256x; 1.2256x over previous
#include <cuda_runtime.h>
#include <math.h>

#define Bb 4
#define Ss 2048
#define Dd 256
#define Rr (Bb*Ss)

// ------------------- scratch (device globals; no allocation) ---------------
__device__ __align__(16) float g_M[Dd*Dd];   // M = Wq^T Wk
__device__ __align__(16) float g_c1[Dd], g_c2[Dd];
__device__ float g_c0;
__device__ float g_mean[Rr], g_inv[Rr];      // LN stats
// per-64-col-slice partial reductions, slot = blockIdx.x (4 slices of D)
__device__ float g_pd[4*Rr], g_pm[4*Rr], g_pa1[4*Rr], g_pa2[4*Rr];
__device__ float g_diag[Rr];
__device__ double g_l[Rr], g_P[Rr];
__device__ int g_lo[Rr], g_hi[Rr];

// ------------------- K1: prologue = LN stats (1024) + M (256) + bias (1) ---
__global__ void prologue_kernel(const float* __restrict__ ctx,
                                const float* __restrict__ Wq,
                                const float* __restrict__ Wk,
                                const float* __restrict__ bq,
                                const float* __restrict__ bk) {
    int bid = blockIdx.x;
    int t = threadIdx.x;
    if (bid < 1024) {
        int w = t >> 5, lane = t & 31;
        int r = bid * 8 + w;
        const float* src = ctx + (size_t)r * Dd;
        float4 v0 = *(const float4*)&src[lane*4];
        float4 v1 = *(const float4*)&src[128 + lane*4];
        float s = v0.x+v0.y+v0.z+v0.w + v1.x+v1.y+v1.z+v1.w;
        #pragma unroll
        for (int o = 16; o; o >>= 1) s += __shfl_xor_sync(0xffffffffu, s, o);
        float mean = s * (1.0f/Dd);
        float d0x=v0.x-mean, d0y=v0.y-mean, d0z=v0.z-mean, d0w=v0.w-mean;
        float d1x=v1.x-mean, d1y=v1.y-mean, d1z=v1.z-mean, d1w=v1.w-mean;
        float sq = d0x*d0x+d0y*d0y+d0z*d0z+d0w*d0w + d1x*d1x+d1y*d1y+d1z*d1z+d1w*d1w;
        #pragma unroll
        for (int o = 16; o; o >>= 1) sq += __shfl_xor_sync(0xffffffffu, sq, o);
        if (lane == 0) {
            g_mean[r] = mean;
            g_inv[r] = 1.0f / (sqrtf(sq * (1.0f/(Dd-1))) + 1e-6f);
        }
    } else if (bid < 1280) {
        __shared__ float sq[16][17], sk[16][17];
        int mb = bid - 1024;
        int bx = mb & 15, by = mb >> 4;
        int tx = t & 15, ty = t >> 4;
        float acc = 0.f;
        for (int f0 = 0; f0 < Dd; f0 += 16) {
            sq[ty][tx] = Wq[(f0+ty)*Dd + by*16 + tx];
            sk[ty][tx] = Wk[(f0+ty)*Dd + bx*16 + tx];
            __syncthreads();
            #pragma unroll
            for (int f = 0; f < 16; ++f) acc += sq[f][ty] * sk[f][tx];
            __syncthreads();
        }
        g_M[(by*16+ty)*Dd + bx*16 + tx] = acc;
    } else {
        __shared__ float red[256];
        float a1 = 0.f, a2 = 0.f;
        for (int f = 0; f < Dd; ++f) {
            a1 += Wq[f*Dd + t] * bk[f];
            a2 += Wk[f*Dd + t] * bq[f];
        }
        g_c1[t] = a1; g_c2[t] = a2;
        red[t] = bq[t] * bk[t];
        __syncthreads();
        for (int s = 128; s; s >>= 1) { if (t < s) red[t] += red[t+s]; __syncthreads(); }
        if (t == 0) g_c0 = red[0];
    }
}

// ------------------- helpers -----------------------------------------------
__device__ __forceinline__ float4 ln4(float4 v, float4 l4, float4 b4, float mn, float iv) {
    return make_float4(l4.x*iv*(v.x-mn)+b4.x, l4.y*iv*(v.y-mn)+b4.y,
                       l4.z*iv*(v.z-mn)+b4.z, l4.w*iv*(v.w-mn)+b4.w);
}
__device__ __forceinline__ float dot4(float4 a, float4 b) {
    return a.x*b.x + a.y*b.y + a.z*b.z + a.w*b.w;
}

// ------------------- K2: GEMM 128x64 tile, 8x4 micro + fused reductions ----
// U[r] = M x_r in registers. Epilogue: u_row.x_{row+1} = dotm[row+1],
// u_row.x_{row-1} = dotp[row-1]  (dotp[r] := x_r^T M x_{r+1} = q_r.k_{r+1}).
__global__ void __launch_bounds__(256) gemm_kernel(const float* __restrict__ ctx,
                                                   const float* __restrict__ la,
                                                   const float* __restrict__ lb) {
    __shared__ __align__(16) float As[16][132];
    __shared__ __align__(16) float Bs[16][68];
    int tid = threadIdx.x;
    int tx = tid & 15;     // 4 output cols each (64 total)
    int ty = tid >> 4;     // 8 output rows each (128 total)
    int d0 = blockIdx.x * 64;
    int r0 = blockIdx.y * 128;

    // A loads: 2 float4/thread; B loads: 1 float4/thread
    int rowA[2], segA[2];
    float mnA[2], ivA[2];
    #pragma unroll
    for (int s = 0; s < 2; ++s) {
        int idx = tid + s*256;
        rowA[s] = idx >> 2; segA[s] = (idx & 3) * 4;
        mnA[s] = g_mean[r0 + rowA[s]];
        ivA[s] = g_inv[r0 + rowA[s]];
    }
    int rowB = tid >> 2, segB = (tid & 3) * 4;

    float acc[8][4] = {};
    float4 pa[2], pb;

    #pragma unroll
    for (int s = 0; s < 2; ++s) {
        float4 v  = *(const float4*)&ctx[(size_t)(r0+rowA[s])*Dd + segA[s]];
        float4 l4 = *(const float4*)&la[segA[s]];
        float4 b4 = *(const float4*)&lb[segA[s]];
        pa[s] = ln4(v, l4, b4, mnA[s], ivA[s]);
    }
    pb = *(const float4*)&g_M[(size_t)(d0+rowB)*Dd + segB];

    for (int e0 = 0; e0 < Dd; e0 += 16) {
        #pragma unroll
        for (int s = 0; s < 2; ++s) {
            int row = rowA[s], seg = segA[s];
            As[seg+0][row] = pa[s].x; As[seg+1][row] = pa[s].y;
            As[seg+2][row] = pa[s].z; As[seg+3][row] = pa[s].w;
        }
        Bs[segB+0][rowB] = pb.x; Bs[segB+1][rowB] = pb.y;
        Bs[segB+2][rowB] = pb.z; Bs[segB+3][rowB] = pb.w;
        __syncthreads();
        if (e0 + 16 < Dd) {
            #pragma unroll
            for (int s = 0; s < 2; ++s) {
                int e = e0 + 16 + segA[s];
                float4 v  = *(const float4*)&ctx[(size_t)(r0+rowA[s])*Dd + e];
                float4 l4 = *(const float4*)&la[e];
                float4 b4 = *(const float4*)&lb[e];
                pa[s] = ln4(v, l4, b4, mnA[s], ivA[s]);
            }
            pb = *(const float4*)&g_M[(size_t)(d0+rowB)*Dd + e0 + 16 + segB];
        }
        #pragma unroll
        for (int k = 0; k < 16; ++k) {
            float4 a0 = *(const float4*)&As[k][ty*8];
            float4 a1 = *(const float4*)&As[k][ty*8 + 4];
            float4 bb = *(const float4*)&Bs[k][tx*4];
            float av[8] = {a0.x,a0.y,a0.z,a0.w, a1.x,a1.y,a1.z,a1.w};
            float bv[4] = {bb.x,bb.y,bb.z,bb.w};
            #pragma unroll
            for (int i2 = 0; i2 < 8; ++i2)
                #pragma unroll
                for (int j2 = 0; j2 < 4; ++j2) acc[i2][j2] += av[i2]*bv[j2];
        }
        __syncthreads();
    }

    // ---- epilogue: fused per-row reductions over this block's 64 cols -----
    int cA = d0 + tx*4;
    float4 laA = *(const float4*)&la[cA];
    float4 lbA = *(const float4*)&lb[cA];
    float4 c1A = *(const float4*)&g_c1[cA];
    float4 c2A = *(const float4*)&g_c2[cA];
    size_t pbase = (size_t)blockIdx.x * Rr;

    #pragma unroll
    for (int i2 = 0; i2 < 8; ++i2) {
        int row = r0 + ty*8 + i2;
        const float* u = acc[i2];

        float mn = g_mean[row], iv = g_inv[row];
        float4 xA = ln4(*(const float4*)&ctx[(size_t)row*Dd + cA], laA, lbA, mn, iv);
        float pa1 = dot4(xA, c1A);
        float pa2 = dot4(xA, c2A);

        int rp = (row + 1 < Rr) ? row + 1 : Rr - 1;   // clamped load; store guarded
        float mnp = g_mean[rp], ivp = g_inv[rp];
        float4 ppA = ln4(*(const float4*)&ctx[(size_t)rp*Dd + cA], laA, lbA, mnp, ivp);
        float dmv = u[0]*ppA.x + u[1]*ppA.y + u[2]*ppA.z + u[3]*ppA.w;  // -> dotm[row+1]

        int rm = (row - 1 >= 0) ? row - 1 : 0;        // clamped load; store guarded
        float mnm = g_mean[rm], ivm = g_inv[rm];
        float4 pmA = ln4(*(const float4*)&ctx[(size_t)rm*Dd + cA], laA, lbA, mnm, ivm);
        float dpv = u[0]*pmA.x + u[1]*pmA.y + u[2]*pmA.z + u[3]*pmA.w;  // -> dotp[row-1]

        #pragma unroll
        for (int o = 1; o < 16; o <<= 1) {
            dmv += __shfl_xor_sync(0xffffffffu, dmv, o);
            dpv += __shfl_xor_sync(0xffffffffu, dpv, o);
            pa1 += __shfl_xor_sync(0xffffffffu, pa1, o);
            pa2 += __shfl_xor_sync(0xffffffffu, pa2, o);
        }
        if (tx == 0) {
            g_pa1[pbase + row] = pa1;
            g_pa2[pbase + row] = pa2;
            if (row + 1 < Rr) g_pm[pbase + row + 1] = dmv;  // dotm[row+1]
            if (row - 1 >= 0) g_pd[pbase + row - 1] = dpv;  // dotp[row-1]
        }
    }
}

// ------------------- probs helper (sums the four 64-col partials) ----------
__device__ __forceinline__ void probs(const int* __restrict__ ebase, int i, int r,
                                      float& pp, float& pm, float& ps) {
    bool ap = (i < Ss-1) && (ebase[(size_t)i*Ss + i + 1] != 0);
    bool am = (i > 0)    && (ebase[(size_t)i*Ss + i - 1] != 0);
    if (!ap && !am) { pp = pm = ps = 1.0f/(float)Ss; return; }
    ps = 0.f;
    if (ap && am) {
        float c0 = g_c0;
        float dotp = (g_pd[r]      + g_pd[Rr + r])
                   + (g_pd[2*Rr+r] + g_pd[3*Rr + r]);
        float dotm = (g_pm[r]      + g_pm[Rr + r])
                   + (g_pm[2*Rr+r] + g_pm[3*Rr + r]);
        float a1   = (g_pa1[r]      + g_pa1[Rr + r])
                   + (g_pa1[2*Rr+r] + g_pa1[3*Rr + r]);
        float a2p  = (g_pa2[r+1]      + g_pa2[Rr + r+1])
                   + (g_pa2[2*Rr+r+1] + g_pa2[3*Rr + r+1]);
        float a2m  = (g_pa2[r-1]      + g_pa2[Rr + r-1])
                   + (g_pa2[2*Rr+r-1] + g_pa2[3*Rr + r-1]);
        float sp = (dotp + a1 + a2p + c0) * (1.0f/256.0f);
        float sm = (dotm + a1 + a2m + c0) * (1.0f/256.0f);
        float m = fmaxf(sp, sm);
        float ep = expf(sp - m), em = expf(sm - m);
        float inv = 1.0f/(ep + em);
        pp = ep*inv; pm = em*inv;
    } else if (ap) { pp = 1.f; pm = 0.f; }
    else           { pp = 0.f; pm = 1.f; }
}

// ------------------- K3: wide probs + log + diag ---------------------------
__global__ void lprob_kernel(const int* __restrict__ eos,
                             const float* __restrict__ prior) {
    int r = blockIdx.x*64 + threadIdx.x;
    if (r >= Rr) return;
    int b = r >> 11, i = r & (Ss-1);
    const int* ebase = eos + (size_t)b*Ss*Ss;
    const float* pbase = prior + (size_t)b*Ss*Ss;

    float pp, pm, ps;
    probs(ebase, i, r, pp, pm, ps);

    if (i < Ss-1) {
        float pp2, pm2, ps2;
        probs(ebase, i+1, r+1, pp2, pm2, ps2);
        float n1 = sqrtf(pp*pm2 + 1e-9f);
        float pr = pbase[(size_t)i*Ss + i + 1];
        float nb = pr + (1.0f - pr)*n1;
        g_l[r] = log((double)nb + 1e-9);
    } else {
        g_l[r] = 0.0;
    }
    float nd = sqrtf(ps*ps + 1e-9f);
    float pr = pbase[(size_t)i*Ss + i];
    g_diag[r] = pr + (1.0f - pr)*nd;
}

// ------------------- K4: shuffle-based exclusive scan (f64) ----------------
__global__ void scan_kernel() {
    __shared__ double wsum[32];
    int b = blockIdx.x, t = threadIdx.x;
    int lane = t & 31, w = t >> 5;
    int base = b*Ss;
    double l0 = g_l[base + 2*t];
    double l1 = g_l[base + 2*t + 1];
    double s = l0 + l1;
    double v = s;
    #pragma unroll
    for (int o = 1; o < 32; o <<= 1) {
        double n = __shfl_up_sync(0xffffffffu, v, o);
        if (lane >= o) v += n;
    }
    if (lane == 31) wsum[w] = v;
    __syncthreads();
    if (w == 0) {
        double x = wsum[lane];
        #pragma unroll
        for (int o = 1; o < 32; o <<= 1) {
            double n = __shfl_up_sync(0xffffffffu, x, o);
            if (lane >= o) x += n;
        }
        wsum[lane] = x;
    }
    __syncthreads();
    double off = (w > 0) ? wsum[w-1] : 0.0;
    double excl = off + v - s;
    g_P[base + 2*t]     = excl;
    g_P[base + 2*t + 1] = excl + l0;
}

// ------------------- K5: wide band search (P in L2) ------------------------
__global__ void band_kernel() {
    int r = blockIdx.x*256 + threadIdx.x;
    int b = r >> 11, i = r & (Ss-1);
    const double* P = g_P + b*Ss;
    double Pi = P[i];
    const double T = 46.0;   // exp(-46) ~ 1e-20 << 1e-9 floor

    int lo2 = i, hi2 = Ss-1;
    while (lo2 < hi2) {
        int mid = (lo2 + hi2 + 1) >> 1;
        if (Pi - P[mid] <= T) lo2 = mid; else hi2 = mid - 1;
    }
    int a = 0, b2 = i;
    while (a < b2) {
        int mid = (a + b2) >> 1;
        if (P[mid] - Pi <= T) b2 = mid; else a = mid + 1;
    }
    g_lo[r] = a; g_hi[r] = lo2;
}

// ------------------- K6: banded output, 4 rows/block, float4 ---------------
__global__ void out_kernel(float* __restrict__ out) {
    int r0 = blockIdx.x * 4;
    #pragma unroll
    for (int rr = 0; rr < 4; ++rr) {
        int r = r0 + rr;
        int b = r >> 11, i = r & (Ss-1);
        const double* P = g_P + b*Ss;
        double Pi = P[i];
        int lo = g_lo[r], hi = g_hi[r];
        float dg = g_diag[r];
        float* orow = out + (size_t)r*Ss;
        #pragma unroll
        for (int s = 0; s < 2; ++s) {
            int t = threadIdx.x + s*256;
            int j0 = t*4;
            float4 o;
            if (j0 + 3 < lo || j0 > hi) {
                o = make_float4(1e-9f, 1e-9f, 1e-9f, 1e-9f);
            } else {
                float v[4];
                #pragma unroll
                for (int q = 0; q < 4; ++q) {
                    int j = j0 + q;
                    float x;
                    if (j < lo || j > hi) x = 1e-9f;
                    else if (j == i)      x = dg;
                    else {
                        double e = (j > i) ? (P[j] - Pi) : (Pi - P[j]);
                        x = expf((float)e) + 1e-9f;
                    }
                    v[q] = x;
                }
                o = make_float4(v[0], v[1], v[2], v[3]);
            }
            *(float4*)&orow[j0] = o;
        }
    }
}

// ------------------- launch -------------------------------------------------
extern "C" void kernel_launch(void* const* d_in, const int* in_sizes, int n_in,
                              void* d_out, int out_size) {
    const float* ctx   = (const float*)d_in[0];
    const float* prior = (const float*)d_in[1];
    const float* Wq    = (const float*)d_in[2];
    const float* bq    = (const float*)d_in[3];
    const float* Wk    = (const float*)d_in[4];
    const float* bk    = (const float*)d_in[5];
    const float* la    = (const float*)d_in[6];
    const float* lb    = (const float*)d_in[7];
    const int*   eos   = (const int*)d_in[8];
    float* out = (float*)d_out;

    prologue_kernel<<<1281, 256>>>(ctx, Wq, Wk, bq, bk);
    gemm_kernel<<<dim3(4, Rr/128), 256>>>(ctx, la, lb);
    lprob_kernel<<<Rr/64, 64>>>(eos, prior);
    scan_kernel<<<Bb, 1024>>>();
    band_kernel<<<Rr/256, 256>>>();
    out_kernel<<<Rr/4, 256>>>(out);
}